// round 10
// baseline (speedup 1.0000x reference)
#include <cuda_runtime.h>
#include <cuda_bf16.h>
#include <cstdint>
#include <float.h>

// Problem constants (RaggedTopKGatingModule: N=524288, E=64, K=8)
#define E_EXPERTS 64
#define TOPK 8
#define BLOCK_A 256
#define TOK_PER_BLOCK 128                              // 2 lanes per token
#define SLOTS_PER_CHUNK (TOK_PER_BLOCK * TOPK)         // 1024
#define MAX_SLOTS (524288 * 8)
#define MAX_CHUNKS 4096
#define ROW_B 288                                      // 256B row + 2x16B pad
#define HALF_B 144

// Scratch (no allocation allowed; __device__ globals)
// packed per-slot: (expert_id << 8) | within_chunk_rank   (rank <= 127)
__device__ uint16_t g_pack[MAX_SLOTS];                 // 8 MB
__device__ int      g_chunk_hist[MAX_CHUNKS * E_EXPERTS];
__device__ int      g_chunk_base[MAX_CHUNKS * E_EXPERTS];

// ---------------------------------------------------------------------------
// Kernel A: staged-smem pair-split top-8 (float/fma-pipe sort) + softmax
//           + logits copy + warp-local ordered ranking
// ---------------------------------------------------------------------------
__global__ __launch_bounds__(BLOCK_A, 5)
void topk_rank_kernel(const float* __restrict__ logits,
                      float* __restrict__ out_scores,
                      float* __restrict__ out_logits,
                      int n_tokens)
{
    __shared__ uint8_t  sh_stage[TOK_PER_BLOCK * ROW_B];   // 36 KB
    __shared__ int      sh_cnt[8 * E_EXPERTS];             // 2 KB
    __shared__ int      sh_base[8 * E_EXPERTS];            // 2 KB
    __shared__ uint64_t sh_e64[TOK_PER_BLOCK];             // 1 KB

    const int tid  = threadIdx.x;
    const int lane = tid & 31;
    const int warp = tid >> 5;
    const int chunk = blockIdx.x;
    const int tok_base = chunk * TOK_PER_BLOCK;

    // -------- Phase 0: coalesced copy + padded smem staging --------
    {
        const size_t gbase = (size_t)tok_base * E_EXPERTS;
        const float4* src = (const float4*)(logits + gbase);
        float4*       dst = (float4*)(out_logits + gbase);
        #pragma unroll
        for (int k = 0; k < 8; ++k) {
            const int i = tid + k * BLOCK_A;           // 0..2047 float4
            float4 v = src[i];
            dst[i] = v;
            const int tok = i >> 4, rem = i & 15;
            const int soff = tok * ROW_B + (rem >> 3) * HALF_B + (rem & 7) * 16;
            *(float4*)(sh_stage + soff) = v;
        }
        sh_cnt[tid] = 0; sh_cnt[tid + BLOCK_A] = 0;    // zero warp counters
    }
    __syncthreads();

    // -------- Phase 1: pair-split exact top-8 + softmax --------
    {
        const int lt   = tid >> 1;          // local token 0..127
        const int half = tid & 1;           // 0: experts 0-31, 1: 32-63
        const int t = tok_base + lt;
        uint8_t* myhalf = sh_stage + lt * ROW_B + half * HALF_B;

        float tv[TOPK];
        int   ti[TOPK];
        #pragma unroll
        for (int k = 0; k < TOPK; ++k) { tv[k] = -FLT_MAX; ti[k] = 0; }

        float s0 = 0.f, s1 = 0.f, s2 = 0.f, s3 = 0.f;

        #pragma unroll
        for (int j = 0; j < 8; ++j) {       // 32 experts per lane, from smem
            float4 q = *(const float4*)(myhalf + j * 16);
            float xs[4] = {q.x, q.y, q.z, q.w};
            s0 += __expf(q.x); s1 += __expf(q.y);
            s2 += __expf(q.z); s3 += __expf(q.w);
            #pragma unroll
            for (int u = 0; u < 4; ++u) {
                const int le = j * 4 + u;   // local expert id
                const float x = xs[u];
                // strict >: lowest-index-first on exact ties within half
                if (x > tv[TOPK - 1]) {
                    tv[TOPK - 1] = x; ti[TOPK - 1] = le;
                    #pragma unroll
                    for (int jj = TOPK - 1; jj > 0; --jj) {
                        if (tv[jj] > tv[jj - 1]) {
                            float tf = tv[jj]; tv[jj] = tv[jj - 1]; tv[jj - 1] = tf;
                            int   tt = ti[jj]; ti[jj] = ti[jj - 1]; ti[jj - 1] = tt;
                        }
                    }
                }
            }
        }

        // publish local top-8 IN PLACE into own (already consumed) region
        *(float4*)(myhalf +  0) = make_float4(tv[0], tv[1], tv[2], tv[3]);
        *(float4*)(myhalf + 16) = make_float4(tv[4], tv[5], tv[6], tv[7]);
        uint64_t idp = 0;
        #pragma unroll
        for (int k = 0; k < TOPK; ++k)
            idp |= (uint64_t)(uint8_t)(half * 32 + ti[k]) << (8 * k);
        *(uint64_t*)(myhalf + 32) = idp;

        const float mysum = (s0 + s1) + (s2 + s3);
        const float total = mysum + __shfl_xor_sync(0xffffffffu, mysum, 1);
        __syncwarp();                       // pair's STS visible

        if (!half) {
            const float*   KA = (const float*)(sh_stage + lt * ROW_B);
            const float*   KB = (const float*)(sh_stage + lt * ROW_B + HALF_B);
            const uint8_t* EA = sh_stage + lt * ROW_B + 32;
            const uint8_t* EB = sh_stage + lt * ROW_B + HALF_B + 32;
            const float inv = 1.0f / total;

            float sc[TOPK];
            uint64_t ep = 0;
            int i = 0, j = 0;
            #pragma unroll
            for (int k = 0; k < TOPK; ++k) {
                float ka = (i < 8) ? KA[i] : -FLT_MAX;
                float kb = (j < 8) ? KB[j] : -FLT_MAX;
                // ties -> even half (experts 0-31) = lower index first
                const bool takeA = (ka >= kb);
                const float   kk = takeA ? ka : kb;
                const uint8_t ee = takeA ? EA[i] : EB[j];
                i += takeA; j += !takeA;
                sc[k] = __expf(kk) * inv;
                ep |= (uint64_t)ee << (8 * k);
            }
            sh_e64[lt] = ep;
            float4* srow = (float4*)(out_scores + (size_t)t * TOPK);
            srow[0] = make_float4(sc[0], sc[1], sc[2], sc[3]);
            srow[1] = make_float4(sc[4], sc[5], sc[6], sc[7]);
        }
    }
    __syncthreads();

    // -------- Phase 2: warp-local ordered multisplit (slots 128w..128w+127) --
    const uint8_t* eb = (const uint8_t*)sh_e64;
    const unsigned lanemask_lt = (1u << lane) - 1u;
    int mye[4], myr[4];
    #pragma unroll
    for (int q = 0; q < 4; ++q) {
        const int slot = warp * 128 + q * 32 + lane;   // token-major order
        const int e = eb[slot];
        unsigned mask = __match_any_sync(0xffffffffu, e);
        const int lrank = __popc(mask & lanemask_lt);
        const int prev = sh_cnt[warp * E_EXPERTS + e]; // counts of rounds < q
        mye[q] = e; myr[q] = prev + lrank;
        __syncwarp();
        if (lane == __ffs(mask) - 1)
            sh_cnt[warp * E_EXPERTS + e] = prev + __popc(mask);
        __syncwarp();
    }
    __syncthreads();

    // single cross-warp scan
    if (tid < E_EXPERTS) {
        int run = 0;
        #pragma unroll
        for (int w = 0; w < 8; ++w) {
            sh_base[w * E_EXPERTS + tid] = run;
            run += sh_cnt[w * E_EXPERTS + tid];
        }
        g_chunk_hist[chunk * E_EXPERTS + tid] = run;
    }
    __syncthreads();

    const size_t slot_base = (size_t)chunk * SLOTS_PER_CHUNK;
    #pragma unroll
    for (int q = 0; q < 4; ++q) {
        const int rank = sh_base[warp * E_EXPERTS + mye[q]] + myr[q];  // <=127
        g_pack[slot_base + warp * 128 + q * 32 + lane] =
            (uint16_t)((mye[q] << 8) | rank);
    }
}

// ---------------------------------------------------------------------------
// Kernel B: per-expert exclusive scan over 4096 chunk histograms (4 per thread)
// ---------------------------------------------------------------------------
__global__ void scan_kernel(float* __restrict__ out_counts, int n_chunks)
{
    __shared__ int s[1024];
    const int e = blockIdx.x;
    const int c = threadIdx.x;

    int v[4];
    #pragma unroll
    for (int i = 0; i < 4; ++i) {
        const int ci = 4 * c + i;
        v[i] = (ci < n_chunks) ? g_chunk_hist[ci * E_EXPERTS + e] : 0;
    }
    const int quad = v[0] + v[1] + v[2] + v[3];
    s[c] = quad;
    __syncthreads();

    #pragma unroll
    for (int off = 1; off < 1024; off <<= 1) {
        int t = (c >= off) ? s[c - off] : 0;
        __syncthreads();
        s[c] += t;
        __syncthreads();
    }
    const int incl = s[c];
    int run = incl - quad;
    #pragma unroll
    for (int i = 0; i < 4; ++i) {
        const int ci = 4 * c + i;
        if (ci < n_chunks) g_chunk_base[ci * E_EXPERTS + e] = run;
        run += v[i];
    }
    if (c == 1023) out_counts[e] = (float)incl;
}

// ---------------------------------------------------------------------------
// Kernel C: final offsets + assignments   (8 slots / thread, uint4 pack load)
// ---------------------------------------------------------------------------
__global__ __launch_bounds__(256, 8)
void offsets_kernel(float* __restrict__ out_offs,
                    float* __restrict__ out_assign, int n_oct)
{
    const int o = blockIdx.x * blockDim.x + threadIdx.x;
    if (o >= n_oct) return;
    const int idx = o * 8;                          // 8 | 1024: no chunk cross
    const int chunk = idx >> 10;                    // / SLOTS_PER_CHUNK (1024)
    const int* __restrict__ base = g_chunk_base + chunk * E_EXPERTS;

    uint4 pr = *(const uint4*)(g_pack + idx);       // 8 packed uint16

    const unsigned p0 = pr.x & 0xffffu, p1 = pr.x >> 16;
    const unsigned p2 = pr.y & 0xffffu, p3 = pr.y >> 16;
    const unsigned p4 = pr.z & 0xffffu, p5 = pr.z >> 16;
    const unsigned p6 = pr.w & 0xffffu, p7 = pr.w >> 16;

    const int e0 = p0 >> 8, e1 = p1 >> 8, e2 = p2 >> 8, e3 = p3 >> 8;
    const int e4 = p4 >> 8, e5 = p5 >> 8, e6 = p6 >> 8, e7 = p7 >> 8;

    // issue all 8 gathers up front (MLP=8)
    const int b0 = base[e0], b1 = base[e1], b2 = base[e2], b3 = base[e3];
    const int b4 = base[e4], b5 = base[e5], b6 = base[e6], b7 = base[e7];

    float4 o0, o1, a0, a1;
    o0.x = (float)(b0 + (int)(p0 & 255));  a0.x = (float)e0;
    o0.y = (float)(b1 + (int)(p1 & 255));  a0.y = (float)e1;
    o0.z = (float)(b2 + (int)(p2 & 255));  a0.z = (float)e2;
    o0.w = (float)(b3 + (int)(p3 & 255));  a0.w = (float)e3;
    o1.x = (float)(b4 + (int)(p4 & 255));  a1.x = (float)e4;
    o1.y = (float)(b5 + (int)(p5 & 255));  a1.y = (float)e5;
    o1.z = (float)(b6 + (int)(p6 & 255));  a1.z = (float)e6;
    o1.w = (float)(b7 + (int)(p7 & 255));  a1.w = (float)e7;

    float4* po = (float4*)(out_offs + idx);
    float4* pa = (float4*)(out_assign + idx);
    po[0] = o0; po[1] = o1;
    pa[0] = a0; pa[1] = a1;
}

// ---------------------------------------------------------------------------
extern "C" void kernel_launch(void* const* d_in, const int* in_sizes, int n_in,
                              void* d_out, int out_size)
{
    // inputs: [0]=expert_counts(E), [1]=assignments(N*K), [2]=offsets(N*K), [3]=logits(N*E)
    const float* logits = (const float*)d_in[3];
    const int n_tokens = in_sizes[3] / E_EXPERTS;       // 524288
    const int n_slots  = n_tokens * TOPK;               // 4194304
    const int n_chunks = n_tokens / TOK_PER_BLOCK;      // 4096

    float* out = (float*)d_out;
    // layout: counts[E] | scores[N*K] | assign[N*K] | offs[N*K] | logits[N*E]
    float* out_counts = out;
    float* out_scores = out + E_EXPERTS;
    float* out_assign = out_scores + (size_t)n_slots;
    float* out_offs   = out_assign + (size_t)n_slots;
    float* out_logits = out_offs   + (size_t)n_slots;

    topk_rank_kernel<<<n_chunks, BLOCK_A>>>(logits, out_scores,
                                            out_logits, n_tokens);
    scan_kernel<<<E_EXPERTS, 1024>>>(out_counts, n_chunks);
    const int n_oct = n_slots / 8;
    offsets_kernel<<<(n_oct + 255) / 256, 256>>>(out_offs, out_assign, n_oct);
}

// round 11
// speedup vs baseline: 1.0359x; 1.0359x over previous
#include <cuda_runtime.h>
#include <cuda_bf16.h>
#include <cstdint>
#include <float.h>

// Problem constants (RaggedTopKGatingModule: N=524288, E=64, K=8)
#define E_EXPERTS 64
#define TOPK 8
#define BLOCK_A 256
#define TOK_PER_BLOCK 128                              // 2 lanes per token
#define SLOTS_PER_CHUNK (TOK_PER_BLOCK * TOPK)         // 1024
#define MAX_SLOTS (524288 * 8)
#define MAX_CHUNKS 4096
#define ROW_B 288                                      // 256B row + 2x16B pad
#define HALF_B 144

// Scratch (no allocation allowed; __device__ globals)
// packed per-slot: (expert_id << 8) | within_chunk_rank   (rank <= 127)
__device__ uint16_t g_pack[MAX_SLOTS];                 // 8 MB
__device__ int      g_chunk_hist[MAX_CHUNKS * E_EXPERTS];
__device__ int      g_chunk_base[MAX_CHUNKS * E_EXPERTS];

// ---------------------------------------------------------------------------
// Kernel A: staged-smem pair-split top-8 (float/fma-pipe sort) + softmax
//           + logits copy + warp-local ordered ranking + assign stores
// ---------------------------------------------------------------------------
__global__ __launch_bounds__(BLOCK_A, 5)
void topk_rank_kernel(const float* __restrict__ logits,
                      float* __restrict__ out_scores,
                      float* __restrict__ out_assign,
                      float* __restrict__ out_logits,
                      int n_tokens)
{
    __shared__ uint8_t  sh_stage[TOK_PER_BLOCK * ROW_B];   // 36 KB
    __shared__ int      sh_cnt[8 * E_EXPERTS];             // 2 KB
    __shared__ int      sh_base[8 * E_EXPERTS];            // 2 KB
    __shared__ uint64_t sh_e64[TOK_PER_BLOCK];             // 1 KB

    const int tid  = threadIdx.x;
    const int lane = tid & 31;
    const int warp = tid >> 5;
    const int chunk = blockIdx.x;
    const int tok_base = chunk * TOK_PER_BLOCK;

    // -------- Phase 0: coalesced copy + padded smem staging --------
    {
        const size_t gbase = (size_t)tok_base * E_EXPERTS;
        const float4* src = (const float4*)(logits + gbase);
        float4*       dst = (float4*)(out_logits + gbase);
        #pragma unroll
        for (int k = 0; k < 8; ++k) {
            const int i = tid + k * BLOCK_A;           // 0..2047 float4
            float4 v = src[i];
            dst[i] = v;
            const int tok = i >> 4, rem = i & 15;
            const int soff = tok * ROW_B + (rem >> 3) * HALF_B + (rem & 7) * 16;
            *(float4*)(sh_stage + soff) = v;
        }
        sh_cnt[tid] = 0; sh_cnt[tid + BLOCK_A] = 0;    // zero warp counters
    }
    __syncthreads();

    // -------- Phase 1: pair-split exact top-8 + softmax --------
    {
        const int lt   = tid >> 1;          // local token 0..127
        const int half = tid & 1;           // 0: experts 0-31, 1: 32-63
        const int t = tok_base + lt;
        uint8_t* myhalf = sh_stage + lt * ROW_B + half * HALF_B;

        float tv[TOPK];
        int   ti[TOPK];
        #pragma unroll
        for (int k = 0; k < TOPK; ++k) { tv[k] = -FLT_MAX; ti[k] = 0; }

        float s0 = 0.f, s1 = 0.f, s2 = 0.f, s3 = 0.f;

        #pragma unroll
        for (int j = 0; j < 8; ++j) {       // 32 experts per lane, from smem
            float4 q = *(const float4*)(myhalf + j * 16);
            float xs[4] = {q.x, q.y, q.z, q.w};
            s0 += __expf(q.x); s1 += __expf(q.y);
            s2 += __expf(q.z); s3 += __expf(q.w);
            #pragma unroll
            for (int u = 0; u < 4; ++u) {
                const int le = j * 4 + u;   // local expert id
                const float x = xs[u];
                // strict >: lowest-index-first on exact ties within half
                if (x > tv[TOPK - 1]) {
                    tv[TOPK - 1] = x; ti[TOPK - 1] = le;
                    #pragma unroll
                    for (int jj = TOPK - 1; jj > 0; --jj) {
                        if (tv[jj] > tv[jj - 1]) {
                            float tf = tv[jj]; tv[jj] = tv[jj - 1]; tv[jj - 1] = tf;
                            int   tt = ti[jj]; ti[jj] = ti[jj - 1]; ti[jj - 1] = tt;
                        }
                    }
                }
            }
        }

        // publish local top-8 IN PLACE into own (already consumed) region
        *(float4*)(myhalf +  0) = make_float4(tv[0], tv[1], tv[2], tv[3]);
        *(float4*)(myhalf + 16) = make_float4(tv[4], tv[5], tv[6], tv[7]);
        uint64_t idp = 0;
        #pragma unroll
        for (int k = 0; k < TOPK; ++k)
            idp |= (uint64_t)(uint8_t)(half * 32 + ti[k]) << (8 * k);
        *(uint64_t*)(myhalf + 32) = idp;

        const float mysum = (s0 + s1) + (s2 + s3);
        const float total = mysum + __shfl_xor_sync(0xffffffffu, mysum, 1);
        __syncwarp();                       // pair's STS visible

        if (!half) {
            const float*   KA = (const float*)(sh_stage + lt * ROW_B);
            const float*   KB = (const float*)(sh_stage + lt * ROW_B + HALF_B);
            const uint8_t* EA = sh_stage + lt * ROW_B + 32;
            const uint8_t* EB = sh_stage + lt * ROW_B + HALF_B + 32;
            const float inv = 1.0f / total;

            float sc[TOPK];
            uint64_t ep = 0;
            int i = 0, j = 0;
            #pragma unroll
            for (int k = 0; k < TOPK; ++k) {
                float ka = (i < 8) ? KA[i] : -FLT_MAX;
                float kb = (j < 8) ? KB[j] : -FLT_MAX;
                // ties -> even half (experts 0-31) = lower index first
                const bool takeA = (ka >= kb);
                const float   kk = takeA ? ka : kb;
                const uint8_t ee = takeA ? EA[i] : EB[j];
                i += takeA; j += !takeA;
                sc[k] = __expf(kk) * inv;
                ep |= (uint64_t)ee << (8 * k);
            }
            sh_e64[lt] = ep;
            float4* srow = (float4*)(out_scores + (size_t)t * TOPK);
            srow[0] = make_float4(sc[0], sc[1], sc[2], sc[3]);
            srow[1] = make_float4(sc[4], sc[5], sc[6], sc[7]);
        }
    }
    __syncthreads();

    // -------- Phase 2: warp-local ordered multisplit (slots 128w..128w+127) --
    const uint8_t* eb = (const uint8_t*)sh_e64;
    const unsigned lanemask_lt = (1u << lane) - 1u;
    int mye[4], myr[4];
    #pragma unroll
    for (int q = 0; q < 4; ++q) {
        const int slot = warp * 128 + q * 32 + lane;   // token-major order
        const int e = eb[slot];
        unsigned mask = __match_any_sync(0xffffffffu, e);
        const int lrank = __popc(mask & lanemask_lt);
        const int prev = sh_cnt[warp * E_EXPERTS + e]; // counts of rounds < q
        mye[q] = e; myr[q] = prev + lrank;
        __syncwarp();
        if (lane == __ffs(mask) - 1)
            sh_cnt[warp * E_EXPERTS + e] = prev + __popc(mask);
        __syncwarp();
    }
    __syncthreads();

    // single cross-warp scan
    if (tid < E_EXPERTS) {
        int run = 0;
        #pragma unroll
        for (int w = 0; w < 8; ++w) {
            sh_base[w * E_EXPERTS + tid] = run;
            run += sh_cnt[w * E_EXPERTS + tid];
        }
        g_chunk_hist[chunk * E_EXPERTS + tid] = run;
    }
    __syncthreads();

    const size_t slot_base = (size_t)chunk * SLOTS_PER_CHUNK;
    #pragma unroll
    for (int q = 0; q < 4; ++q) {
        const int s = warp * 128 + q * 32 + lane;
        const int rank = sh_base[warp * E_EXPERTS + mye[q]] + myr[q];  // <=127
        g_pack[slot_base + s] = (uint16_t)((mye[q] << 8) | rank);
        out_assign[slot_base + s] = (float)mye[q];     // coalesced 128B/warp
    }
}

// ---------------------------------------------------------------------------
// Kernel B: per-expert exclusive scan over 4096 chunk histograms (4 per thread)
// ---------------------------------------------------------------------------
__global__ void scan_kernel(float* __restrict__ out_counts, int n_chunks)
{
    __shared__ int s[1024];
    const int e = blockIdx.x;
    const int c = threadIdx.x;

    int v[4];
    #pragma unroll
    for (int i = 0; i < 4; ++i) {
        const int ci = 4 * c + i;
        v[i] = (ci < n_chunks) ? g_chunk_hist[ci * E_EXPERTS + e] : 0;
    }
    const int quad = v[0] + v[1] + v[2] + v[3];
    s[c] = quad;
    __syncthreads();

    #pragma unroll
    for (int off = 1; off < 1024; off <<= 1) {
        int t = (c >= off) ? s[c - off] : 0;
        __syncthreads();
        s[c] += t;
        __syncthreads();
    }
    const int incl = s[c];
    int run = incl - quad;
    #pragma unroll
    for (int i = 0; i < 4; ++i) {
        const int ci = 4 * c + i;
        if (ci < n_chunks) g_chunk_base[ci * E_EXPERTS + e] = run;
        run += v[i];
    }
    if (c == 1023) out_counts[e] = (float)incl;
}

// ---------------------------------------------------------------------------
// Kernel C: final offsets only   (4 slots / thread)
// ---------------------------------------------------------------------------
__global__ __launch_bounds__(256, 8)
void offsets_kernel(float* __restrict__ out_offs, int n_quads)
{
    const int q = blockIdx.x * blockDim.x + threadIdx.x;
    if (q >= n_quads) return;
    const int idx = q * 4;
    const int chunk = idx >> 10;                    // / SLOTS_PER_CHUNK (1024)

    ushort4 p4 = *(const ushort4*)(g_pack + idx);
    const int* __restrict__ base = g_chunk_base + chunk * E_EXPERTS;

    float4 o;
    o.x = (float)(base[p4.x >> 8] + (p4.x & 255));
    o.y = (float)(base[p4.y >> 8] + (p4.y & 255));
    o.z = (float)(base[p4.z >> 8] + (p4.z & 255));
    o.w = (float)(base[p4.w >> 8] + (p4.w & 255));
    *(float4*)(out_offs + idx) = o;
}

// ---------------------------------------------------------------------------
extern "C" void kernel_launch(void* const* d_in, const int* in_sizes, int n_in,
                              void* d_out, int out_size)
{
    // inputs: [0]=expert_counts(E), [1]=assignments(N*K), [2]=offsets(N*K), [3]=logits(N*E)
    const float* logits = (const float*)d_in[3];
    const int n_tokens = in_sizes[3] / E_EXPERTS;       // 524288
    const int n_slots  = n_tokens * TOPK;               // 4194304
    const int n_chunks = n_tokens / TOK_PER_BLOCK;      // 4096

    float* out = (float*)d_out;
    // layout: counts[E] | scores[N*K] | assign[N*K] | offs[N*K] | logits[N*E]
    float* out_counts = out;
    float* out_scores = out + E_EXPERTS;
    float* out_assign = out_scores + (size_t)n_slots;
    float* out_offs   = out_assign + (size_t)n_slots;
    float* out_logits = out_offs   + (size_t)n_slots;

    topk_rank_kernel<<<n_chunks, BLOCK_A>>>(logits, out_scores, out_assign,
                                            out_logits, n_tokens);
    scan_kernel<<<E_EXPERTS, 1024>>>(out_counts, n_chunks);
    const int n_quads = n_slots / 4;
    offsets_kernel<<<(n_quads + 255) / 256, 256>>>(out_offs, n_quads);
}

// round 12
// speedup vs baseline: 1.0429x; 1.0068x over previous
#include <cuda_runtime.h>
#include <cuda_bf16.h>
#include <cstdint>
#include <float.h>

// Problem constants (RaggedTopKGatingModule: N=524288, E=64, K=8)
#define E_EXPERTS 64
#define TOPK 8
#define BLOCK_A 256
#define TOK_PER_BLOCK 128                              // 2 lanes per token
#define SLOTS_PER_CHUNK (TOK_PER_BLOCK * TOPK)         // 1024
#define MAX_SLOTS (524288 * 8)
#define MAX_CHUNKS 4096
#define ROW_B 288                                      // 256B row + 2x16B pad
#define HALF_B 144

// Scratch (no allocation allowed; __device__ globals)
// packed per-slot: (expert_id << 8) | within_chunk_rank   (rank <= 127)
__device__ uint16_t g_pack[MAX_SLOTS];                 // 8 MB
__device__ int      g_chunk_hist[MAX_CHUNKS * E_EXPERTS];
__device__ int      g_chunk_base[MAX_CHUNKS * E_EXPERTS];

// ---------------------------------------------------------------------------
// Kernel A: staged-smem pair-split top-8 (float/fma-pipe sort) + softmax
//           + logits copy + warp-local ordered ranking + assign stores
//   smem: cnt/base tables overlaid into dead stage region -> 37KB, 6 CTAs/SM
// ---------------------------------------------------------------------------
__global__ __launch_bounds__(BLOCK_A, 6)
void topk_rank_kernel(const float* __restrict__ logits,
                      float* __restrict__ out_scores,
                      float* __restrict__ out_assign,
                      float* __restrict__ out_logits,
                      int n_tokens)
{
    __shared__ uint8_t  sh_stage[TOK_PER_BLOCK * ROW_B];   // 36 KB
    __shared__ uint64_t sh_e64[TOK_PER_BLOCK];             // 1 KB

    // phase-2-only tables overlaid into sh_stage (dead after phase-1 merge)
    int* sh_cnt  = (int*)sh_stage;                  // 8*64 ints = 2 KB
    int* sh_base = (int*)(sh_stage + 2048);         // 8*64 ints = 2 KB

    const int tid  = threadIdx.x;
    const int lane = tid & 31;
    const int warp = tid >> 5;
    const int chunk = blockIdx.x;
    const int tok_base = chunk * TOK_PER_BLOCK;

    // -------- Phase 0: coalesced copy + padded smem staging --------
    {
        const size_t gbase = (size_t)tok_base * E_EXPERTS;
        const float4* src = (const float4*)(logits + gbase);
        float4*       dst = (float4*)(out_logits + gbase);
        #pragma unroll
        for (int k = 0; k < 8; ++k) {
            const int i = tid + k * BLOCK_A;           // 0..2047 float4
            float4 v = src[i];
            dst[i] = v;
            const int tok = i >> 4, rem = i & 15;
            const int soff = tok * ROW_B + (rem >> 3) * HALF_B + (rem & 7) * 16;
            *(float4*)(sh_stage + soff) = v;
        }
    }
    __syncthreads();

    // -------- Phase 1: pair-split exact top-8 + softmax --------
    {
        const int lt   = tid >> 1;          // local token 0..127
        const int half = tid & 1;           // 0: experts 0-31, 1: 32-63
        const int t = tok_base + lt;
        uint8_t* myhalf = sh_stage + lt * ROW_B + half * HALF_B;

        float tv[TOPK];
        int   ti[TOPK];
        #pragma unroll
        for (int k = 0; k < TOPK; ++k) { tv[k] = -FLT_MAX; ti[k] = 0; }

        float s0 = 0.f, s1 = 0.f, s2 = 0.f, s3 = 0.f;

        #pragma unroll
        for (int j = 0; j < 8; ++j) {       // 32 experts per lane, from smem
            float4 q = *(const float4*)(myhalf + j * 16);
            float xs[4] = {q.x, q.y, q.z, q.w};
            s0 += __expf(q.x); s1 += __expf(q.y);
            s2 += __expf(q.z); s3 += __expf(q.w);
            #pragma unroll
            for (int u = 0; u < 4; ++u) {
                const int le = j * 4 + u;   // local expert id
                const float x = xs[u];
                // strict >: lowest-index-first on exact ties within half
                if (x > tv[TOPK - 1]) {
                    tv[TOPK - 1] = x; ti[TOPK - 1] = le;
                    #pragma unroll
                    for (int jj = TOPK - 1; jj > 0; --jj) {
                        if (tv[jj] > tv[jj - 1]) {
                            float tf = tv[jj]; tv[jj] = tv[jj - 1]; tv[jj - 1] = tf;
                            int   tt = ti[jj]; ti[jj] = ti[jj - 1]; ti[jj - 1] = tt;
                        }
                    }
                }
            }
        }

        // publish local top-8 IN PLACE into own (already consumed) region
        *(float4*)(myhalf +  0) = make_float4(tv[0], tv[1], tv[2], tv[3]);
        *(float4*)(myhalf + 16) = make_float4(tv[4], tv[5], tv[6], tv[7]);
        uint64_t idp = 0;
        #pragma unroll
        for (int k = 0; k < TOPK; ++k)
            idp |= (uint64_t)(uint8_t)(half * 32 + ti[k]) << (8 * k);
        *(uint64_t*)(myhalf + 32) = idp;

        const float mysum = (s0 + s1) + (s2 + s3);
        const float total = mysum + __shfl_xor_sync(0xffffffffu, mysum, 1);
        __syncwarp();                       // pair's STS visible

        if (!half) {
            const float*   KA = (const float*)(sh_stage + lt * ROW_B);
            const float*   KB = (const float*)(sh_stage + lt * ROW_B + HALF_B);
            const uint8_t* EA = sh_stage + lt * ROW_B + 32;
            const uint8_t* EB = sh_stage + lt * ROW_B + HALF_B + 32;
            const float inv = 1.0f / total;

            float sc[TOPK];
            uint64_t ep = 0;
            int i = 0, j = 0;
            #pragma unroll
            for (int k = 0; k < TOPK; ++k) {
                float ka = (i < 8) ? KA[i] : -FLT_MAX;
                float kb = (j < 8) ? KB[j] : -FLT_MAX;
                // ties -> even half (experts 0-31) = lower index first
                const bool takeA = (ka >= kb);
                const float   kk = takeA ? ka : kb;
                const uint8_t ee = takeA ? EA[i] : EB[j];
                i += takeA; j += !takeA;
                sc[k] = __expf(kk) * inv;
                ep |= (uint64_t)ee << (8 * k);
            }
            sh_e64[lt] = ep;
            float4* srow = (float4*)(out_scores + (size_t)t * TOPK);
            srow[0] = make_float4(sc[0], sc[1], sc[2], sc[3]);
            srow[1] = make_float4(sc[4], sc[5], sc[6], sc[7]);
        }
    }
    __syncthreads();                        // merge reads of stage complete

    // zero overlaid warp counters (stage region now dead)
    sh_cnt[tid] = 0; sh_cnt[tid + BLOCK_A] = 0;
    __syncthreads();

    // -------- Phase 2: warp-local ordered multisplit (slots 128w..128w+127) --
    const uint8_t* eb = (const uint8_t*)sh_e64;
    const unsigned lanemask_lt = (1u << lane) - 1u;
    int mye[4], myr[4];
    #pragma unroll
    for (int q = 0; q < 4; ++q) {
        const int slot = warp * 128 + q * 32 + lane;   // token-major order
        const int e = eb[slot];
        unsigned mask = __match_any_sync(0xffffffffu, e);
        const int lrank  = __popc(mask & lanemask_lt);
        const int leader = __ffs(mask) - 1;
        int prev = 0;
        if (lane == leader) {               // leader-only RMW: program-ordered
            prev = sh_cnt[warp * E_EXPERTS + e];
            sh_cnt[warp * E_EXPERTS + e] = prev + __popc(mask);
        }
        prev = __shfl_sync(0xffffffffu, prev, leader);
        mye[q] = e; myr[q] = prev + lrank;
        __syncwarp();                       // order leader STS before next round
    }
    __syncthreads();

    // single cross-warp scan
    if (tid < E_EXPERTS) {
        int run = 0;
        #pragma unroll
        for (int w = 0; w < 8; ++w) {
            sh_base[w * E_EXPERTS + tid] = run;
            run += sh_cnt[w * E_EXPERTS + tid];
        }
        g_chunk_hist[chunk * E_EXPERTS + tid] = run;
    }
    __syncthreads();

    const size_t slot_base = (size_t)chunk * SLOTS_PER_CHUNK;
    #pragma unroll
    for (int q = 0; q < 4; ++q) {
        const int s = warp * 128 + q * 32 + lane;
        const int rank = sh_base[warp * E_EXPERTS + mye[q]] + myr[q];  // <=127
        g_pack[slot_base + s] = (uint16_t)((mye[q] << 8) | rank);
        out_assign[slot_base + s] = (float)mye[q];     // coalesced 128B/warp
    }
}

// ---------------------------------------------------------------------------
// Kernel B: per-expert exclusive scan over 4096 chunk histograms (4 per thread)
// ---------------------------------------------------------------------------
__global__ void scan_kernel(float* __restrict__ out_counts, int n_chunks)
{
    __shared__ int s[1024];
    const int e = blockIdx.x;
    const int c = threadIdx.x;

    int v[4];
    #pragma unroll
    for (int i = 0; i < 4; ++i) {
        const int ci = 4 * c + i;
        v[i] = (ci < n_chunks) ? g_chunk_hist[ci * E_EXPERTS + e] : 0;
    }
    const int quad = v[0] + v[1] + v[2] + v[3];
    s[c] = quad;
    __syncthreads();

    #pragma unroll
    for (int off = 1; off < 1024; off <<= 1) {
        int t = (c >= off) ? s[c - off] : 0;
        __syncthreads();
        s[c] += t;
        __syncthreads();
    }
    const int incl = s[c];
    int run = incl - quad;
    #pragma unroll
    for (int i = 0; i < 4; ++i) {
        const int ci = 4 * c + i;
        if (ci < n_chunks) g_chunk_base[ci * E_EXPERTS + e] = run;
        run += v[i];
    }
    if (c == 1023) out_counts[e] = (float)incl;
}

// ---------------------------------------------------------------------------
// Kernel C: final offsets only   (4 slots / thread)
// ---------------------------------------------------------------------------
__global__ __launch_bounds__(256, 8)
void offsets_kernel(float* __restrict__ out_offs, int n_quads)
{
    const int q = blockIdx.x * blockDim.x + threadIdx.x;
    if (q >= n_quads) return;
    const int idx = q * 4;
    const int chunk = idx >> 10;                    // / SLOTS_PER_CHUNK (1024)

    ushort4 p4 = *(const ushort4*)(g_pack + idx);
    const int* __restrict__ base = g_chunk_base + chunk * E_EXPERTS;

    float4 o;
    o.x = (float)(base[p4.x >> 8] + (p4.x & 255));
    o.y = (float)(base[p4.y >> 8] + (p4.y & 255));
    o.z = (float)(base[p4.z >> 8] + (p4.z & 255));
    o.w = (float)(base[p4.w >> 8] + (p4.w & 255));
    *(float4*)(out_offs + idx) = o;
}

// ---------------------------------------------------------------------------
extern "C" void kernel_launch(void* const* d_in, const int* in_sizes, int n_in,
                              void* d_out, int out_size)
{
    // inputs: [0]=expert_counts(E), [1]=assignments(N*K), [2]=offsets(N*K), [3]=logits(N*E)
    const float* logits = (const float*)d_in[3];
    const int n_tokens = in_sizes[3] / E_EXPERTS;       // 524288
    const int n_slots  = n_tokens * TOPK;               // 4194304
    const int n_chunks = n_tokens / TOK_PER_BLOCK;      // 4096

    float* out = (float*)d_out;
    // layout: counts[E] | scores[N*K] | assign[N*K] | offs[N*K] | logits[N*E]
    float* out_counts = out;
    float* out_scores = out + E_EXPERTS;
    float* out_assign = out_scores + (size_t)n_slots;
    float* out_offs   = out_assign + (size_t)n_slots;
    float* out_logits = out_offs   + (size_t)n_slots;

    topk_rank_kernel<<<n_chunks, BLOCK_A>>>(logits, out_scores, out_assign,
                                            out_logits, n_tokens);
    scan_kernel<<<E_EXPERTS, 1024>>>(out_counts, n_chunks);
    const int n_quads = n_slots / 4;
    offsets_kernel<<<(n_quads + 255) / 256, 256>>>(out_offs, n_quads);
}